// round 3
// baseline (speedup 1.0000x reference)
#include <cuda_runtime.h>
#include <cuda_bf16.h>
#include <cstdint>

// Problem dims
#define BATCH 8192
#define INF   784
#define HID   4096
#define OUTF  10
#define KC    1600           // padded concat K: [0,784)=hi, [784,1568)=lo, rest 0

// GEMM1 tiling
#define BM 128
#define BN 128
#define BK 64                // 64 bf16 = 128B rows (SW128 atom)
#define NCH (KC / BK)        // 25 chunks
#define STAGES 3

#define A_BYTES (BM * 128)   // 16384
#define B_BYTES (BN * 128)   // 16384
#define STAGE_BYTES (A_BYTES + B_BYTES)          // 32768
#define SMEM_TOTAL  (STAGES * STAGE_BYTES)       // 98304

// -------------------- scratch (allowed: __device__ globals) --------------------
__device__ __align__(128) __nv_bfloat16 g_Xc[(size_t)BATCH * KC];
__device__ __align__(128) __nv_bfloat16 g_Sc[(size_t)HID * KC];
__device__ __align__(128) float         g_h [(size_t)BATCH * HID];

// -------------------- PTX helpers (compute_100 baseline only) --------------------
__device__ __forceinline__ uint32_t smem_u32(const void* p) {
    uint32_t a;
    asm("{ .reg .u64 t; cvta.to.shared.u64 t, %1; cvt.u32.u64 %0, t; }" : "=r"(a) : "l"(p));
    return a;
}
__device__ __forceinline__ uint32_t swz128(uint32_t off) {
    return off ^ ((off >> 3) & 0x70u);
}
__device__ __forceinline__ void cp16(uint32_t dst, const void* src) {
    asm volatile("cp.async.cg.shared.global [%0], [%1], 16;\n" :: "r"(dst), "l"(src));
}
__device__ __forceinline__ void cp_commit() {
    asm volatile("cp.async.commit_group;\n" ::: "memory");
}
__device__ __forceinline__ void ldsm_x4(uint32_t& r0, uint32_t& r1, uint32_t& r2, uint32_t& r3,
                                        uint32_t addr) {
    asm volatile("ldmatrix.sync.aligned.m8n8.x4.shared.b16 {%0,%1,%2,%3}, [%4];"
                 : "=r"(r0), "=r"(r1), "=r"(r2), "=r"(r3) : "r"(addr));
}
__device__ __forceinline__ void mma16816(float* c, uint32_t a0, uint32_t a1, uint32_t a2,
                                         uint32_t a3, uint32_t b0, uint32_t b1) {
    asm volatile("mma.sync.aligned.m16n8k16.row.col.f32.bf16.bf16.f32 "
                 "{%0,%1,%2,%3}, {%4,%5,%6,%7}, {%8,%9}, {%0,%1,%2,%3};"
                 : "+f"(c[0]), "+f"(c[1]), "+f"(c[2]), "+f"(c[3])
                 : "r"(a0), "r"(a1), "r"(a2), "r"(a3), "r"(b0), "r"(b1));
}

// -------------------- prep kernels --------------------
__global__ void prep_x_kernel(const float* __restrict__ x) {
    size_t idx = (size_t)blockIdx.x * blockDim.x + threadIdx.x;
    size_t total = (size_t)BATCH * KC;
    if (idx >= total) return;
    int row = (int)(idx / KC);
    int col = (int)(idx % KC);
    __nv_bfloat16 v;
    if (col < INF) {
        v = __float2bfloat16_rn(x[(size_t)row * INF + col]);
    } else if (col < 2 * INF) {
        float f = x[(size_t)row * INF + (col - INF)];
        float hi = __bfloat162float(__float2bfloat16_rn(f));
        v = __float2bfloat16_rn(f - hi);
    } else {
        v = __float2bfloat16_rn(0.0f);
    }
    g_Xc[idx] = v;
}

__global__ void prep_w_kernel(const float* __restrict__ W1) {
    size_t idx = (size_t)blockIdx.x * blockDim.x + threadIdx.x;
    size_t total = (size_t)HID * KC;
    if (idx >= total) return;
    int row = (int)(idx / KC);
    int col = (int)(idx % KC);
    float s = 0.0f;
    if (col < 2 * INF) {
        int k = (col < INF) ? col : (col - INF);
        float w = W1[(size_t)row * INF + k];
        s = (w > 0.0f) ? 1.0f : ((w < 0.0f) ? -1.0f : 0.0f);
    }
    g_Sc[idx] = __float2bfloat16_rn(s);
}

// -------------------- GEMM1: h = clip(Xcat @ Scat^T + b1) --------------------
// 256 threads = 8 warps as 2(M) x 4(N); warp tile 64x32; mma m16n8k16 bf16.
__device__ __forceinline__ void load_chunk(uint32_t sbase, int stage, int kc,
                                           int m0, int n0, int tid) {
    uint32_t sa = sbase + stage * STAGE_BYTES;
    uint32_t sb = sa + A_BYTES;
    const __nv_bfloat16* gA = g_Xc + (size_t)m0 * KC + kc * BK;
    const __nv_bfloat16* gB = g_Sc + (size_t)n0 * KC + kc * BK;
#pragma unroll
    for (int i = 0; i < 4; i++) {                 // A: 128 rows x 8 chunks of 16B
        int id = i * 256 + tid;
        int r = id >> 3, s = id & 7;
        cp16(sa + swz128((uint32_t)(r * 128 + s * 16)), gA + (size_t)r * KC + s * 8);
    }
#pragma unroll
    for (int i = 0; i < 4; i++) {                 // B: 128 rows x 8 chunks of 16B
        int id = i * 256 + tid;
        int r = id >> 3, s = id & 7;
        cp16(sb + swz128((uint32_t)(r * 128 + s * 16)), gB + (size_t)r * KC + s * 8);
    }
}

__global__ void __launch_bounds__(256, 2) gemm1_kernel(const float* __restrict__ b1) {
    extern __shared__ char dsm[];
    const int tid  = threadIdx.x;
    const int lane = tid & 31;
    const int wid  = tid >> 5;
    const int wm   = wid & 1;       // 0..1 -> M offset wm*64
    const int wn   = wid >> 1;      // 0..3 -> N offset wn*32
    const int m0 = blockIdx.x * BM;
    const int n0 = blockIdx.y * BN;
    const uint32_t sbase = smem_u32(dsm);

    // per-thread ldmatrix base byte offsets (pre-swizzle)
    const uint32_t aoff0 = (uint32_t)((wm * 64 + (lane & 15)) * 128 + (lane >> 4) * 16);
    const uint32_t boff0 = (uint32_t)((wn * 32 + (lane & 7) + ((lane >> 4) << 3)) * 128
                                      + ((lane >> 3) & 1) * 16);

    float acc[4][4][4];
#pragma unroll
    for (int mf = 0; mf < 4; mf++)
#pragma unroll
        for (int nf = 0; nf < 4; nf++)
#pragma unroll
            for (int i = 0; i < 4; i++) acc[mf][nf][i] = 0.0f;

    // prologue
    load_chunk(sbase, 0, 0, m0, n0, tid); cp_commit();
    load_chunk(sbase, 1, 1, m0, n0, tid); cp_commit();

    int stage = 0;
    for (int j = 0; j < NCH; j++) {
        asm volatile("cp.async.wait_group 1;\n" ::: "memory");
        __syncthreads();

        // prefetch chunk j+2 into the slot freed by chunk j-1
        int jn = j + 2;
        if (jn < NCH) {
            int sn = stage + 2; if (sn >= STAGES) sn -= STAGES;
            load_chunk(sbase, sn, jn, m0, n0, tid);
        }
        cp_commit();   // always commit: keeps group bookkeeping uniform

        // compute chunk j from 'stage'
        uint32_t sa = sbase + stage * STAGE_BYTES;
        uint32_t sb = sa + A_BYTES;
#pragma unroll
        for (int kk = 0; kk < 4; kk++) {
            uint32_t af[4][4];
            uint32_t bf[4][2];
#pragma unroll
            for (int mf = 0; mf < 4; mf++) {
                uint32_t off = aoff0 + (uint32_t)(mf * 2048 + kk * 32);
                ldsm_x4(af[mf][0], af[mf][1], af[mf][2], af[mf][3], sa + swz128(off));
            }
#pragma unroll
            for (int p = 0; p < 2; p++) {   // pairs of n8-frags via x4
                uint32_t off = boff0 + (uint32_t)(p * 2048 + kk * 32);
                uint32_t r0, r1, r2, r3;
                ldsm_x4(r0, r1, r2, r3, sb + swz128(off));
                bf[2 * p][0] = r0;  bf[2 * p][1] = r1;
                bf[2 * p + 1][0] = r2; bf[2 * p + 1][1] = r3;
            }
#pragma unroll
            for (int mf = 0; mf < 4; mf++)
#pragma unroll
                for (int nf = 0; nf < 4; nf++)
                    mma16816(acc[mf][nf], af[mf][0], af[mf][1], af[mf][2], af[mf][3],
                             bf[nf][0], bf[nf][1]);
        }
        __syncthreads();
        stage++; if (stage >= STAGES) stage = 0;
    }

    // epilogue: add b1, clip, store float2 (coalesced 32B sectors)
    const int rbase = m0 + wm * 64 + (lane >> 2);
    const int cbase = n0 + wn * 32 + (lane & 3) * 2;
#pragma unroll
    for (int mf = 0; mf < 4; mf++) {
#pragma unroll
        for (int nf = 0; nf < 4; nf++) {
            int col = cbase + nf * 8;
            float bb0 = __ldg(b1 + col), bb1 = __ldg(b1 + col + 1);
#pragma unroll
            for (int half = 0; half < 2; half++) {
                int row = rbase + mf * 16 + half * 8;
                float v0 = acc[mf][nf][2 * half]     + bb0;
                float v1 = acc[mf][nf][2 * half + 1] + bb1;
                v0 = fminf(1.0f, fmaxf(-1.0f, v0));
                v1 = fminf(1.0f, fmaxf(-1.0f, v1));
                *(float2*)(g_h + (size_t)row * HID + col) = make_float2(v0, v1);
            }
        }
    }
}

// -------------------- FC2: out = h @ W2^T + b2 --------------------
#define ROWS_PER_WARP 4
__global__ void __launch_bounds__(256) fc2_kernel(const float* __restrict__ W2,
                                                  const float* __restrict__ b2,
                                                  float* __restrict__ out) {
    int gwarp = (blockIdx.x * blockDim.x + threadIdx.x) >> 5;
    int lane = threadIdx.x & 31;
    int r0 = gwarp * ROWS_PER_WARP;
    if (r0 >= BATCH) return;

    float acc[ROWS_PER_WARP][OUTF];
#pragma unroll
    for (int r = 0; r < ROWS_PER_WARP; r++)
#pragma unroll
        for (int o = 0; o < OUTF; o++) acc[r][o] = 0.0f;

    const float4* W2v = (const float4*)W2;
#pragma unroll 4
    for (int it = 0; it < HID / 128; it++) {
        int kb = it * 128 + lane * 4;
        int kv = kb >> 2;
        float4 h[ROWS_PER_WARP];
#pragma unroll
        for (int r = 0; r < ROWS_PER_WARP; r++)
            h[r] = *(const float4*)(g_h + (size_t)(r0 + r) * HID + kb);
#pragma unroll
        for (int o = 0; o < OUTF; o++) {
            float4 w = W2v[o * (HID / 4) + kv];
#pragma unroll
            for (int r = 0; r < ROWS_PER_WARP; r++)
                acc[r][o] += h[r].x * w.x + h[r].y * w.y + h[r].z * w.z + h[r].w * w.w;
        }
    }
#pragma unroll
    for (int r = 0; r < ROWS_PER_WARP; r++)
#pragma unroll
        for (int o = 0; o < OUTF; o++)
#pragma unroll
            for (int off = 16; off > 0; off >>= 1)
                acc[r][o] += __shfl_xor_sync(0xFFFFFFFFu, acc[r][o], off);
    if (lane == 0) {
#pragma unroll
        for (int r = 0; r < ROWS_PER_WARP; r++)
#pragma unroll
            for (int o = 0; o < OUTF; o++)
                out[(size_t)(r0 + r) * OUTF + o] = acc[r][o] + b2[o];
    }
}

// -------------------- launch --------------------
extern "C" void kernel_launch(void* const* d_in, const int* in_sizes, int n_in,
                              void* d_out, int out_size) {
    const float* x  = (const float*)d_in[0];
    const float* W1 = (const float*)d_in[1];
    const float* b1 = (const float*)d_in[2];
    const float* W2 = (const float*)d_in[3];
    const float* b2 = (const float*)d_in[4];
    float* out = (float*)d_out;

    cudaFuncSetAttribute(gemm1_kernel, cudaFuncAttributeMaxDynamicSharedMemorySize, SMEM_TOTAL);

    {
        size_t total = (size_t)BATCH * KC;
        prep_x_kernel<<<(unsigned)((total + 255) / 256), 256>>>(x);
    }
    {
        size_t total = (size_t)HID * KC;
        prep_w_kernel<<<(unsigned)((total + 255) / 256), 256>>>(W1);
    }
    gemm1_kernel<<<dim3(BATCH / BM, HID / BN), 256, SMEM_TOTAL>>>(b1);
    fc2_kernel<<<BATCH / (ROWS_PER_WARP * 8), 256>>>(W2, b2, out);
}

// round 4
// speedup vs baseline: 1.1478x; 1.1478x over previous
#include <cuda_runtime.h>
#include <cuda_bf16.h>
#include <cstdint>

// Problem dims
#define BATCH 8192
#define INF   784
#define HID   4096
#define OUTF  10
#define KC    1600           // padded concat K: [0,784)=hi, [784,1568)=lo, rest 0

// GEMM1 tiling: CTA 128x128x64, 4 warps, warp tile 64x64
#define BM 128
#define BN 128
#define BK 64                // 64 bf16 = 128B rows (SW128 atom)
#define NCH (KC / BK)        // 25 chunks
#define STAGES 3

#define A_BYTES (BM * 128)   // 16384
#define B_BYTES (BN * 128)   // 16384
#define STAGE_BYTES (A_BYTES + B_BYTES)          // 32768
#define SMEM_TOTAL  (STAGES * STAGE_BYTES)       // 98304 (2 CTAs/SM fits 192K < 228K)

// -------------------- scratch (allowed: __device__ globals) --------------------
__device__ __align__(128) __nv_bfloat16 g_Xc[(size_t)BATCH * KC];
__device__ __align__(128) __nv_bfloat16 g_Sc[(size_t)HID * KC];
__device__ __align__(128) float         g_h [(size_t)BATCH * HID];

// -------------------- PTX helpers (compute_100 baseline only) --------------------
__device__ __forceinline__ uint32_t smem_u32(const void* p) {
    uint32_t a;
    asm("{ .reg .u64 t; cvta.to.shared.u64 t, %1; cvt.u32.u64 %0, t; }" : "=r"(a) : "l"(p));
    return a;
}
__device__ __forceinline__ uint32_t swz128(uint32_t off) {
    return off ^ ((off >> 3) & 0x70u);
}
__device__ __forceinline__ void cp16(uint32_t dst, const void* src) {
    asm volatile("cp.async.cg.shared.global [%0], [%1], 16;\n" :: "r"(dst), "l"(src));
}
__device__ __forceinline__ void cp_commit() {
    asm volatile("cp.async.commit_group;\n" ::: "memory");
}
__device__ __forceinline__ void ldsm_x4(uint32_t& r0, uint32_t& r1, uint32_t& r2, uint32_t& r3,
                                        uint32_t addr) {
    asm volatile("ldmatrix.sync.aligned.m8n8.x4.shared.b16 {%0,%1,%2,%3}, [%4];"
                 : "=r"(r0), "=r"(r1), "=r"(r2), "=r"(r3) : "r"(addr));
}
__device__ __forceinline__ void mma16816(float* c, uint32_t a0, uint32_t a1, uint32_t a2,
                                         uint32_t a3, uint32_t b0, uint32_t b1) {
    asm volatile("mma.sync.aligned.m16n8k16.row.col.f32.bf16.bf16.f32 "
                 "{%0,%1,%2,%3}, {%4,%5,%6,%7}, {%8,%9}, {%0,%1,%2,%3};"
                 : "+f"(c[0]), "+f"(c[1]), "+f"(c[2]), "+f"(c[3])
                 : "r"(a0), "r"(a1), "r"(a2), "r"(a3), "r"(b0), "r"(b1));
}

// -------------------- prep kernels --------------------
__global__ void prep_x_kernel(const float* __restrict__ x) {
    size_t idx = (size_t)blockIdx.x * blockDim.x + threadIdx.x;
    size_t total = (size_t)BATCH * KC;
    if (idx >= total) return;
    int row = (int)(idx / KC);
    int col = (int)(idx % KC);
    __nv_bfloat16 v;
    if (col < INF) {
        v = __float2bfloat16_rn(x[(size_t)row * INF + col]);
    } else if (col < 2 * INF) {
        float f = x[(size_t)row * INF + (col - INF)];
        float hi = __bfloat162float(__float2bfloat16_rn(f));
        v = __float2bfloat16_rn(f - hi);
    } else {
        v = __float2bfloat16_rn(0.0f);
    }
    g_Xc[idx] = v;
}

__global__ void prep_w_kernel(const float* __restrict__ W1) {
    size_t idx = (size_t)blockIdx.x * blockDim.x + threadIdx.x;
    size_t total = (size_t)HID * KC;
    if (idx >= total) return;
    int row = (int)(idx / KC);
    int col = (int)(idx % KC);
    float s = 0.0f;
    if (col < 2 * INF) {
        int k = (col < INF) ? col : (col - INF);
        float w = W1[(size_t)row * INF + k];
        s = (w > 0.0f) ? 1.0f : ((w < 0.0f) ? -1.0f : 0.0f);
    }
    g_Sc[idx] = __float2bfloat16_rn(s);
}

// -------------------- GEMM1: h = clip(Xcat @ Scat^T + b1) --------------------
// 128 threads = 4 warps as 2(M) x 2(N); warp tile 64x64; mma m16n8k16 bf16.
__device__ __forceinline__ void load_chunk(uint32_t sbase, int stage, int kc,
                                           int m0, int n0, int tid) {
    uint32_t sa = sbase + stage * STAGE_BYTES;
    uint32_t sb = sa + A_BYTES;
    const __nv_bfloat16* gA = g_Xc + (size_t)m0 * KC + kc * BK;
    const __nv_bfloat16* gB = g_Sc + (size_t)n0 * KC + kc * BK;
#pragma unroll
    for (int i = 0; i < 8; i++) {                 // A: 128 rows x 8 chunks of 16B
        int id = i * 128 + tid;
        int r = id >> 3, s = id & 7;
        cp16(sa + swz128((uint32_t)(r * 128 + s * 16)), gA + (size_t)r * KC + s * 8);
    }
#pragma unroll
    for (int i = 0; i < 8; i++) {                 // B: 128 rows x 8 chunks of 16B
        int id = i * 128 + tid;
        int r = id >> 3, s = id & 7;
        cp16(sb + swz128((uint32_t)(r * 128 + s * 16)), gB + (size_t)r * KC + s * 8);
    }
}

__global__ void __launch_bounds__(128, 2) gemm1_kernel(const float* __restrict__ b1) {
    extern __shared__ char dsm[];
    const int tid  = threadIdx.x;
    const int lane = tid & 31;
    const int wid  = tid >> 5;
    const int wm   = wid & 1;        // M offset wm*64
    const int wn   = (wid >> 1) & 1; // N offset wn*64
    const int m0 = blockIdx.x * BM;
    const int n0 = blockIdx.y * BN;
    const uint32_t sbase = smem_u32(dsm);

    // per-thread ldmatrix base byte offsets (pre-swizzle)
    const uint32_t aoff0 = (uint32_t)((wm * 64 + (lane & 15)) * 128 + (lane >> 4) * 16);
    const uint32_t boff0 = (uint32_t)((wn * 64 + (lane & 7) + ((lane >> 4) << 3)) * 128
                                      + ((lane >> 3) & 1) * 16);

    float acc[4][8][4];
#pragma unroll
    for (int mf = 0; mf < 4; mf++)
#pragma unroll
        for (int nf = 0; nf < 8; nf++)
#pragma unroll
            for (int i = 0; i < 4; i++) acc[mf][nf][i] = 0.0f;

    // prologue
    load_chunk(sbase, 0, 0, m0, n0, tid); cp_commit();
    load_chunk(sbase, 1, 1, m0, n0, tid); cp_commit();

    int stage = 0;
    for (int j = 0; j < NCH; j++) {
        asm volatile("cp.async.wait_group 1;\n" ::: "memory");
        __syncthreads();   // single sync: orders prev compute before slot reuse AND data visibility

        // prefetch chunk j+2 into the slot freed by chunk j-1
        int jn = j + 2;
        if (jn < NCH) {
            int sn = stage + 2; if (sn >= STAGES) sn -= STAGES;
            load_chunk(sbase, sn, jn, m0, n0, tid);
        }
        cp_commit();   // always commit: keeps group bookkeeping uniform

        // compute chunk j from 'stage'
        uint32_t sa = sbase + stage * STAGE_BYTES;
        uint32_t sb = sa + A_BYTES;
#pragma unroll
        for (int kk = 0; kk < 4; kk++) {
            uint32_t af[4][4];
            uint32_t bf[8][2];
#pragma unroll
            for (int mf = 0; mf < 4; mf++) {
                uint32_t off = aoff0 + (uint32_t)(mf * 2048 + kk * 32);
                ldsm_x4(af[mf][0], af[mf][1], af[mf][2], af[mf][3], sa + swz128(off));
            }
#pragma unroll
            for (int p = 0; p < 4; p++) {   // pairs of n8-frags via x4
                uint32_t off = boff0 + (uint32_t)(p * 2048 + kk * 32);
                uint32_t r0, r1, r2, r3;
                ldsm_x4(r0, r1, r2, r3, sb + swz128(off));
                bf[2 * p][0] = r0;  bf[2 * p][1] = r1;
                bf[2 * p + 1][0] = r2; bf[2 * p + 1][1] = r3;
            }
#pragma unroll
            for (int mf = 0; mf < 4; mf++)
#pragma unroll
                for (int nf = 0; nf < 8; nf++)
                    mma16816(acc[mf][nf], af[mf][0], af[mf][1], af[mf][2], af[mf][3],
                             bf[nf][0], bf[nf][1]);
        }
        stage++; if (stage >= STAGES) stage = 0;
    }

    // epilogue: add b1, clip, store float2 (coalesced 32B sectors)
    const int rbase = m0 + wm * 64 + (lane >> 2);
    const int cbase = n0 + wn * 64 + (lane & 3) * 2;
#pragma unroll
    for (int mf = 0; mf < 4; mf++) {
#pragma unroll
        for (int nf = 0; nf < 8; nf++) {
            int col = cbase + nf * 8;
            float bb0 = __ldg(b1 + col), bb1 = __ldg(b1 + col + 1);
#pragma unroll
            for (int half = 0; half < 2; half++) {
                int row = rbase + mf * 16 + half * 8;
                float v0 = acc[mf][nf][2 * half]     + bb0;
                float v1 = acc[mf][nf][2 * half + 1] + bb1;
                v0 = fminf(1.0f, fmaxf(-1.0f, v0));
                v1 = fminf(1.0f, fmaxf(-1.0f, v1));
                *(float2*)(g_h + (size_t)row * HID + col) = make_float2(v0, v1);
            }
        }
    }
}

// -------------------- FC2: out = h @ W2^T + b2 --------------------
// 1 warp handles 2 rows; software-pipelined h prefetch; 512 blocks for occupancy.
#define ROWS_PER_WARP 2
__global__ void __launch_bounds__(256) fc2_kernel(const float* __restrict__ W2,
                                                  const float* __restrict__ b2,
                                                  float* __restrict__ out) {
    int gwarp = (blockIdx.x * blockDim.x + threadIdx.x) >> 5;
    int lane = threadIdx.x & 31;
    int r0 = gwarp * ROWS_PER_WARP;
    if (r0 >= BATCH) return;

    const float4* h0p = (const float4*)(g_h + (size_t)r0 * HID);
    const float4* h1p = (const float4*)(g_h + (size_t)(r0 + 1) * HID);
    const float4* W2v = (const float4*)W2;

    float acc[ROWS_PER_WARP][OUTF];
#pragma unroll
    for (int r = 0; r < ROWS_PER_WARP; r++)
#pragma unroll
        for (int o = 0; o < OUTF; o++) acc[r][o] = 0.0f;

    float4 ha = h0p[lane];
    float4 hb = h1p[lane];
#pragma unroll 2
    for (int it = 0; it < HID / 128; it++) {
        int kv = it * 32 + lane;
        float4 cA = ha, cB = hb;
        if (it + 1 < HID / 128) {          // prefetch next iter's h while doing FMAs
            ha = h0p[kv + 32];
            hb = h1p[kv + 32];
        }
#pragma unroll
        for (int o = 0; o < OUTF; o++) {
            float4 w = W2v[o * (HID / 4) + kv];
            acc[0][o] += cA.x * w.x + cA.y * w.y + cA.z * w.z + cA.w * w.w;
            acc[1][o] += cB.x * w.x + cB.y * w.y + cB.z * w.z + cB.w * w.w;
        }
    }
#pragma unroll
    for (int r = 0; r < ROWS_PER_WARP; r++)
#pragma unroll
        for (int o = 0; o < OUTF; o++)
#pragma unroll
            for (int off = 16; off > 0; off >>= 1)
                acc[r][o] += __shfl_xor_sync(0xFFFFFFFFu, acc[r][o], off);
    if (lane == 0) {
#pragma unroll
        for (int r = 0; r < ROWS_PER_WARP; r++)
#pragma unroll
            for (int o = 0; o < OUTF; o++)
                out[(size_t)(r0 + r) * OUTF + o] = acc[r][o] + b2[o];
    }
}

// -------------------- launch --------------------
extern "C" void kernel_launch(void* const* d_in, const int* in_sizes, int n_in,
                              void* d_out, int out_size) {
    const float* x  = (const float*)d_in[0];
    const float* W1 = (const float*)d_in[1];
    const float* b1 = (const float*)d_in[2];
    const float* W2 = (const float*)d_in[3];
    const float* b2 = (const float*)d_in[4];
    float* out = (float*)d_out;

    cudaFuncSetAttribute(gemm1_kernel, cudaFuncAttributeMaxDynamicSharedMemorySize, SMEM_TOTAL);

    {
        size_t total = (size_t)BATCH * KC;
        prep_x_kernel<<<(unsigned)((total + 255) / 256), 256>>>(x);
    }
    {
        size_t total = (size_t)HID * KC;
        prep_w_kernel<<<(unsigned)((total + 255) / 256), 256>>>(W1);
    }
    gemm1_kernel<<<dim3(BATCH / BM, HID / BN), 128, SMEM_TOTAL>>>(b1);
    fc2_kernel<<<BATCH / (ROWS_PER_WARP * 8), 256>>>(W2, b2, out);
}

// round 5
// speedup vs baseline: 1.1939x; 1.0402x over previous
#include <cuda_runtime.h>
#include <cuda_bf16.h>
#include <cstdint>

// Problem dims
#define BATCH 8192
#define INF   784
#define HID   4096
#define OUTF  10

// int8 limb layout: 3 limbs, each K padded 784 -> 896 (7 chunks of 128B)
#define KSB   896            // S (weight) row bytes
#define KXB   2688           // X row bytes = 3 * 896
#define LIMB_CH 7
#define NCH   21             // total K chunks (3 limbs x 7)

// GEMM1 tiling: CTA 128x128, 4 warps, warp tile 64x64, BK=128 int8
#define BM 128
#define BN 128
#define STAGES 3
#define A_BYTES (BM * 128)   // 16384
#define B_BYTES (BN * 128)   // 16384
#define STAGE_BYTES (A_BYTES + B_BYTES)          // 32768
#define SMEM_TOTAL  (STAGES * STAGE_BYTES)       // 98304 -> 2 CTAs/SM

// -------------------- scratch (allowed: __device__ globals) --------------------
__device__ __align__(128) signed char g_Xq[(size_t)BATCH * KXB];
__device__ __align__(128) signed char g_Sq[(size_t)HID * KSB];
__device__ __align__(128) float       g_h [(size_t)BATCH * HID];

// -------------------- PTX helpers (compute_100 baseline only) --------------------
__device__ __forceinline__ uint32_t smem_u32(const void* p) {
    uint32_t a;
    asm("{ .reg .u64 t; cvta.to.shared.u64 t, %1; cvt.u32.u64 %0, t; }" : "=r"(a) : "l"(p));
    return a;
}
__device__ __forceinline__ uint32_t swz128(uint32_t off) {
    return off ^ ((off >> 3) & 0x70u);
}
__device__ __forceinline__ void cp16(uint32_t dst, const void* src) {
    asm volatile("cp.async.cg.shared.global [%0], [%1], 16;\n" :: "r"(dst), "l"(src));
}
__device__ __forceinline__ void cp_commit() {
    asm volatile("cp.async.commit_group;\n" ::: "memory");
}
__device__ __forceinline__ void ldsm_x4(uint32_t& r0, uint32_t& r1, uint32_t& r2, uint32_t& r3,
                                        uint32_t addr) {
    asm volatile("ldmatrix.sync.aligned.m8n8.x4.shared.b16 {%0,%1,%2,%3}, [%4];"
                 : "=r"(r0), "=r"(r1), "=r"(r2), "=r"(r3) : "r"(addr));
}
__device__ __forceinline__ void imma16832(int* c, uint32_t a0, uint32_t a1, uint32_t a2,
                                          uint32_t a3, uint32_t b0, uint32_t b1) {
    asm volatile("mma.sync.aligned.m16n8k32.row.col.s32.s8.s8.s32 "
                 "{%0,%1,%2,%3}, {%4,%5,%6,%7}, {%8,%9}, {%0,%1,%2,%3};"
                 : "+r"(c[0]), "+r"(c[1]), "+r"(c[2]), "+r"(c[3])
                 : "r"(a0), "r"(a1), "r"(a2), "r"(a3), "r"(b0), "r"(b1));
}

// -------------------- prep kernels --------------------
// x = a*2^-4 + b*2^-11 + c*2^-18 + eps, |eps| <= 2^-19; limbs exact in int8.
__global__ void prep_x_kernel(const float* __restrict__ x) {
    size_t idx = (size_t)blockIdx.x * blockDim.x + threadIdx.x;
    size_t total = (size_t)BATCH * KXB;
    if (idx >= total) return;
    int row = (int)(idx / KXB);
    int col = (int)(idx % KXB);
    int limb = col / KSB;
    int k = col - limb * KSB;
    signed char v = 0;
    if (k < INF) {
        float f = x[(size_t)row * INF + k];
        float a = rintf(f * 16.0f);
        if (limb == 0) {
            v = (signed char)(int)a;
        } else {
            float r1 = fmaf(a, -0.0625f, f);
            float b = rintf(r1 * 2048.0f);
            if (limb == 1) {
                v = (signed char)(int)b;
            } else {
                float r2 = fmaf(b, -4.8828125e-4f, r1);
                float c = rintf(r2 * 262144.0f);
                v = (signed char)(int)c;
            }
        }
    }
    g_Xq[idx] = v;
}

__global__ void prep_w_kernel(const float* __restrict__ W1) {
    size_t idx = (size_t)blockIdx.x * blockDim.x + threadIdx.x;
    size_t total = (size_t)HID * KSB;
    if (idx >= total) return;
    int row = (int)(idx / KSB);
    int col = (int)(idx % KSB);
    signed char s = 0;
    if (col < INF) {
        float w = W1[(size_t)row * INF + col];
        s = (w > 0.0f) ? 1 : ((w < 0.0f) ? -1 : 0);
    }
    g_Sq[idx] = s;
}

// -------------------- GEMM1 (int8 limbs): h = clip(acc*2^-18 + b1) --------------------
__device__ __forceinline__ void load_chunk(uint32_t sbase, int stage, int kc,
                                           int m0, int n0, int tid) {
    uint32_t sa = sbase + stage * STAGE_BYTES;
    uint32_t sb = sa + A_BYTES;
    int kcs = kc; if (kcs >= 2 * LIMB_CH) kcs -= 2 * LIMB_CH; else if (kcs >= LIMB_CH) kcs -= LIMB_CH;
    const signed char* gA = g_Xq + (size_t)m0 * KXB + (size_t)kc * 128;
    const signed char* gB = g_Sq + (size_t)n0 * KSB + (size_t)kcs * 128;
#pragma unroll
    for (int i = 0; i < 8; i++) {                 // A: 128 rows x 8 x 16B
        int id = i * 128 + tid;
        int r = id >> 3, s = id & 7;
        cp16(sa + swz128((uint32_t)(r * 128 + s * 16)), gA + (size_t)r * KXB + s * 16);
    }
#pragma unroll
    for (int i = 0; i < 8; i++) {                 // B: 128 rows x 8 x 16B
        int id = i * 128 + tid;
        int r = id >> 3, s = id & 7;
        cp16(sb + swz128((uint32_t)(r * 128 + s * 16)), gB + (size_t)r * KSB + s * 16);
    }
}

__global__ void __launch_bounds__(128, 2) gemm1_kernel(const float* __restrict__ b1) {
    extern __shared__ char dsm[];
    const int tid  = threadIdx.x;
    const int lane = tid & 31;
    const int wid  = tid >> 5;
    const int wm   = wid & 1;        // M offset wm*64
    const int wn   = (wid >> 1) & 1; // N offset wn*64
    const int m0 = blockIdx.x * BM;
    const int n0 = blockIdx.y * BN;
    const uint32_t sbase = smem_u32(dsm);

    // per-thread ldmatrix base byte offsets (pre-swizzle); s8-k32 layout matches
    // the same lane->addr map as bf16-k16 (16B units along K)
    const uint32_t aoff0 = (uint32_t)((wm * 64 + (lane & 15)) * 128 + (lane >> 4) * 16);
    const uint32_t boff0 = (uint32_t)((wn * 64 + (lane & 7) + ((lane >> 4) << 3)) * 128
                                      + ((lane >> 3) & 1) * 16);

    int acc[4][8][4];
#pragma unroll
    for (int mf = 0; mf < 4; mf++)
#pragma unroll
        for (int nf = 0; nf < 8; nf++)
#pragma unroll
            for (int i = 0; i < 4; i++) acc[mf][nf][i] = 0;

    // prologue
    load_chunk(sbase, 0, 0, m0, n0, tid); cp_commit();
    load_chunk(sbase, 1, 1, m0, n0, tid); cp_commit();

    int stage = 0;
    for (int j = 0; j < NCH; j++) {
        asm volatile("cp.async.wait_group 1;\n" ::: "memory");
        __syncthreads();

        int jn = j + 2;
        if (jn < NCH) {
            int sn = stage + 2; if (sn >= STAGES) sn -= STAGES;
            load_chunk(sbase, sn, jn, m0, n0, tid);
        }
        cp_commit();

        // limb boundary: shift accumulated value up by 2^7 (exact, no overflow)
        if (j == LIMB_CH || j == 2 * LIMB_CH) {
#pragma unroll
            for (int mf = 0; mf < 4; mf++)
#pragma unroll
                for (int nf = 0; nf < 8; nf++)
#pragma unroll
                    for (int i = 0; i < 4; i++) acc[mf][nf][i] <<= 7;
        }

        // compute chunk j (128 int8 of K = 4 k32 steps)
        uint32_t sa = sbase + stage * STAGE_BYTES;
        uint32_t sb = sa + A_BYTES;
#pragma unroll
        for (int kk = 0; kk < 4; kk++) {
            uint32_t af[4][4];
            uint32_t bf[8][2];
#pragma unroll
            for (int mf = 0; mf < 4; mf++) {
                uint32_t off = aoff0 + (uint32_t)(mf * 2048 + kk * 32);
                ldsm_x4(af[mf][0], af[mf][1], af[mf][2], af[mf][3], sa + swz128(off));
            }
#pragma unroll
            for (int p = 0; p < 4; p++) {
                uint32_t off = boff0 + (uint32_t)(p * 2048 + kk * 32);
                uint32_t r0, r1, r2, r3;
                ldsm_x4(r0, r1, r2, r3, sb + swz128(off));
                bf[2 * p][0] = r0;  bf[2 * p][1] = r1;
                bf[2 * p + 1][0] = r2; bf[2 * p + 1][1] = r3;
            }
#pragma unroll
            for (int mf = 0; mf < 4; mf++)
#pragma unroll
                for (int nf = 0; nf < 8; nf++)
                    imma16832(acc[mf][nf], af[mf][0], af[mf][1], af[mf][2], af[mf][3],
                              bf[nf][0], bf[nf][1]);
        }
        stage++; if (stage >= STAGES) stage = 0;
    }

    // epilogue: h = clip(float(acc)*2^-18 + b1)
    const float SC = 3.814697265625e-06f;   // 2^-18
    const int rbase = m0 + wm * 64 + (lane >> 2);
    const int cbase = n0 + wn * 64 + (lane & 3) * 2;
#pragma unroll
    for (int mf = 0; mf < 4; mf++) {
#pragma unroll
        for (int nf = 0; nf < 8; nf++) {
            int col = cbase + nf * 8;
            float bb0 = __ldg(b1 + col), bb1 = __ldg(b1 + col + 1);
#pragma unroll
            for (int half = 0; half < 2; half++) {
                int row = rbase + mf * 16 + half * 8;
                float v0 = fmaf((float)acc[mf][nf][2 * half],     SC, bb0);
                float v1 = fmaf((float)acc[mf][nf][2 * half + 1], SC, bb1);
                v0 = fminf(1.0f, fmaxf(-1.0f, v0));
                v1 = fminf(1.0f, fmaxf(-1.0f, v1));
                *(float2*)(g_h + (size_t)row * HID + col) = make_float2(v0, v1);
            }
        }
    }
}

// -------------------- FC2: out = h @ W2^T + b2 (1 row per warp, high MLP) -----------
__global__ void __launch_bounds__(256) fc2_kernel(const float* __restrict__ W2,
                                                  const float* __restrict__ b2,
                                                  float* __restrict__ out) {
    int row = (blockIdx.x * blockDim.x + threadIdx.x) >> 5;
    int lane = threadIdx.x & 31;
    if (row >= BATCH) return;

    const float4* hp  = (const float4*)(g_h + (size_t)row * HID);
    const float4* W2v = (const float4*)W2;

    float acc[OUTF];
#pragma unroll
    for (int o = 0; o < OUTF; o++) acc[o] = 0.0f;

    float4 cur = hp[lane];
#pragma unroll 4
    for (int i = 0; i < HID / 128; i++) {       // 32 iters, lane covers 4 floats each
        float4 h4 = cur;
        int kv = i * 32 + lane;
        if (i + 1 < HID / 128) cur = hp[kv + 32];   // prefetch next h
#pragma unroll
        for (int o = 0; o < OUTF; o++) {
            float4 w = W2v[o * (HID / 4) + kv];
            acc[o] += h4.x * w.x + h4.y * w.y + h4.z * w.z + h4.w * w.w;
        }
    }
#pragma unroll
    for (int o = 0; o < OUTF; o++)
#pragma unroll
        for (int off = 16; off > 0; off >>= 1)
            acc[o] += __shfl_xor_sync(0xFFFFFFFFu, acc[o], off);
    if (lane == 0) {
#pragma unroll
        for (int o = 0; o < OUTF; o++)
            out[(size_t)row * OUTF + o] = acc[o] + b2[o];
    }
}

// -------------------- launch --------------------
extern "C" void kernel_launch(void* const* d_in, const int* in_sizes, int n_in,
                              void* d_out, int out_size) {
    const float* x  = (const float*)d_in[0];
    const float* W1 = (const float*)d_in[1];
    const float* b1 = (const float*)d_in[2];
    const float* W2 = (const float*)d_in[3];
    const float* b2 = (const float*)d_in[4];
    float* out = (float*)d_out;

    cudaFuncSetAttribute(gemm1_kernel, cudaFuncAttributeMaxDynamicSharedMemorySize, SMEM_TOTAL);

    {
        size_t total = (size_t)BATCH * KXB;
        prep_x_kernel<<<(unsigned)((total + 255) / 256), 256>>>(x);
    }
    {
        size_t total = (size_t)HID * KSB;
        prep_w_kernel<<<(unsigned)((total + 255) / 256), 256>>>(W1);
    }
    gemm1_kernel<<<dim3(BATCH / BM, HID / BN), 128, SMEM_TOTAL>>>(b1);
    fc2_kernel<<<(BATCH * 32) / 256, 256>>>(W2, b2, out);
}